// round 9
// baseline (speedup 1.0000x reference)
#include <cuda_runtime.h>
#include <cuda_bf16.h>
#include <cstdint>

// DotInteraction: x [16384, 64, 128] fp32 -> upper-tri gram [16384, 2016] fp32.
// mma.sync m16n8k16 bf16 + ldmatrix (tcgen05 unavailable: harness targets sm_103 w/o 'a').
// Precision: x = hi + lo (bf16); D = hh + hl + lh, fp32 accumulate (rel err ~4e-6).
// R9: intra-CTA k-chunk pipeline (4 chunks of k=32) in the SAME 32KB smem footprint:
//   LDG(c+2) issued before the barrier, cvt+STS(c+1) and compute(c) overlap the
//   DRAM latency -> continuous DRAM issuance per CTA. 6 CTAs/SM preserved.
// Swizzle: byte(r, kc16) = (kc>>3)<<13 | r<<7 | (((kc&7)^(r&7))<<4)  [SW128 blocked atoms]

#define FF 64
#define NPAIR 2016

constexpr int MATB = 64 * 128 * 2;   // 16384 B per bf16 matrix, swizzled
constexpr int SM_TOTAL = 2 * MATB;   // [H][L] = 32768 B

__device__ __forceinline__ uint32_t smem_u32(const void* p) {
    uint32_t a;
    asm("{ .reg .u64 t; cvta.to.shared.u64 t, %1; cvt.u32.u64 %0, t; }" : "=r"(a) : "l"(p));
    return a;
}
__device__ __forceinline__ void ldsm_x4(uint32_t* r, uint32_t addr) {
    asm volatile("ldmatrix.sync.aligned.m8n8.x4.shared.b16 {%0,%1,%2,%3}, [%4];"
                 : "=r"(r[0]), "=r"(r[1]), "=r"(r[2]), "=r"(r[3]) : "r"(addr));
}
__device__ __forceinline__ void mma_bf16(float* c, const uint32_t* a, const uint32_t* b) {
    asm volatile(
        "mma.sync.aligned.m16n8k16.row.col.f32.bf16.bf16.f32 "
        "{%0,%1,%2,%3}, {%4,%5,%6,%7}, {%8,%9}, {%0,%1,%2,%3};"
        : "+f"(c[0]), "+f"(c[1]), "+f"(c[2]), "+f"(c[3])
        : "r"(a[0]), "r"(a[1]), "r"(a[2]), "r"(a[3]), "r"(b[0]), "r"(b[1]));
}
__device__ __forceinline__ uint32_t cvt_bf16x2(float hi, float lo) {
    uint32_t r;
    asm("cvt.rn.bf16x2.f32 %0, %1, %2;" : "=r"(r) : "f"(hi), "f"(lo));
    return r;
}

// ---- chunk load: chunk c = float4 cols [8c, 8c+8); thread covers 4 of them ----
__device__ __forceinline__ void ldg_chunk(const float4* __restrict__ xg, int c, int tid,
                                          float4* p) {
    const float4* base = xg + (size_t)(tid >> 1) * 32 + c * 8 + (tid & 1) * 4;
#pragma unroll
    for (int j = 0; j < 4; ++j) p[j] = base[j];
}

// ---- convert + STS one chunk into swizzled H/L buffers ----
__device__ __forceinline__ void sts_chunk(char* smem, int c, int tid, const float4* p) {
    const int r = tid >> 1;
#pragma unroll
    for (int j = 0; j < 4; ++j) {
        int f4col = c * 8 + (tid & 1) * 4 + j;
        int kc = f4col >> 1;
        int sub = (f4col & 1) << 3;
        float4 v = p[j];

        uint32_t hp0 = cvt_bf16x2(v.y, v.x);
        uint32_t hp1 = cvt_bf16x2(v.w, v.z);
        float h0 = __uint_as_float(hp0 << 16);
        float h1 = __uint_as_float(hp0 & 0xffff0000u);
        float h2 = __uint_as_float(hp1 << 16);
        float h3 = __uint_as_float(hp1 & 0xffff0000u);
        uint32_t lp0 = cvt_bf16x2(v.y - h1, v.x - h0);
        uint32_t lp1 = cvt_bf16x2(v.w - h3, v.z - h2);

        uint32_t off = ((uint32_t)(kc >> 3) << 13) + ((uint32_t)r << 7) +
                       ((uint32_t)(((kc & 7) ^ (r & 7)) << 4)) + (uint32_t)sub;
        *reinterpret_cast<uint2*>(smem + off) = make_uint2(hp0, hp1);
        *reinterpret_cast<uint2*>(smem + MATB + off) = make_uint2(lp0, lp1);
    }
}

// ---- compute chunk C (kk = 2C, 2C+1) for col-pair CP x row-stripes RT0..RT0+NS-1 ----
template <int RT0, int NS, int CP, int C>
__device__ __forceinline__ void grp_chunk(float (&acc)[NS][8], uint32_t sb, int lid) {
    const int hA = lid >> 4;
    const int rA = RT0 * 16 + (lid & 15);
    const uint32_t mA4 = (uint32_t)(((rA & 7) ^ hA) << 4);
    const uint32_t abase = sb + (uint32_t)(rA << 7);
    const int qB = (lid >> 3) & 1;
    const int nx = lid & 7;
    const int nB = CP * 16 + (hA << 3) + nx;
    const uint32_t mB4 = (uint32_t)((nx ^ qB) << 4);
    const uint32_t bbase = sb + (uint32_t)(nB << 7);

#pragma unroll
    for (int kk = 2 * C; kk < 2 * C + 2; ++kk) {
        const uint32_t koff = (uint32_t)((kk >> 2) << 13);
        const uint32_t cb = (uint32_t)(((2 * kk) & 7) << 4);
        const uint32_t bOff = bbase + koff + (cb ^ mB4);
        uint32_t bh[4], bl[4];
        ldsm_x4(bh, bOff);
        ldsm_x4(bl, bOff + MATB);
#pragma unroll
        for (int s = 0; s < NS; ++s) {
            const uint32_t aOff = abase + (uint32_t)(s * 2048) + koff + (cb ^ mA4);
            uint32_t ah[4], al[4];
            ldsm_x4(ah, aOff);
            ldsm_x4(al, aOff + MATB);
            mma_bf16(acc[s] + 0, ah, bh + 0);
            mma_bf16(acc[s] + 0, ah, bl + 0);
            mma_bf16(acc[s] + 0, al, bh + 0);
            mma_bf16(acc[s] + 4, ah, bh + 2);
            mma_bf16(acc[s] + 4, ah, bl + 2);
            mma_bf16(acc[s] + 4, al, bh + 2);
        }
    }
}

// ---- epilogue for one group ----
template <int RT0, int NS, int CP>
__device__ __forceinline__ void store_grp(const float (&acc)[NS][8], float* __restrict__ ob,
                                          int lid) {
    const int rb0 = (lid >> 2);
    const int cb0 = 2 * (lid & 3);
#pragma unroll
    for (int s = 0; s < NS; ++s) {
        const bool diag = (RT0 + s == CP);
        const int ib = (RT0 + s) * 16 + rb0;
#pragma unroll
        for (int cc = 0; cc < 2; ++cc) {
            const int j0 = 8 * (2 * CP + cc) + cb0;
#pragma unroll
            for (int half = 0; half < 2; ++half) {
                const int i = ib + 8 * half;
                const int rowoff = i * (2 * FF - i - 1) / 2 - i - 1;  // out idx = rowoff + j
#pragma unroll
                for (int d = 0; d < 2; ++d) {
                    const int j = j0 + d;
                    if (!diag || j > i) ob[rowoff + j] = acc[s][4 * cc + 2 * half + d];
                }
            }
        }
    }
}

// ---- per-warp pipelined main: two groups (second optional via NS1=0) ----
template <int RT0, int NS0, int CP0, int RT1, int NS1, int CP1>
__device__ __forceinline__ void warp_main(uint32_t sb, char* smem,
                                          const float4* __restrict__ xg,
                                          float* __restrict__ ob, int tid, int lid) {
    float acc0[NS0][8];
    float acc1[NS1 ? NS1 : 1][8];
#pragma unroll
    for (int s = 0; s < NS0; ++s)
#pragma unroll
        for (int e = 0; e < 8; ++e) acc0[s][e] = 0.0f;
    if constexpr (NS1 > 0) {
#pragma unroll
        for (int s = 0; s < NS1; ++s)
#pragma unroll
            for (int e = 0; e < 8; ++e) acc1[s][e] = 0.0f;
    }

    float4 p0[4], p1[4];
    // prologue: c0 load+stage, c1 load in flight
    ldg_chunk(xg, 0, tid, p0);
    sts_chunk(smem, 0, tid, p0);
    ldg_chunk(xg, 1, tid, p1);
    __syncthreads();

    // c = 0
    grp_chunk<RT0, NS0, CP0, 0>(acc0, sb, lid);
    if constexpr (NS1 > 0) grp_chunk<RT1, NS1, CP1, 0>(acc1, sb, lid);
    sts_chunk(smem, 1, tid, p1);
    ldg_chunk(xg, 2, tid, p0);
    __syncthreads();

    // c = 1
    grp_chunk<RT0, NS0, CP0, 1>(acc0, sb, lid);
    if constexpr (NS1 > 0) grp_chunk<RT1, NS1, CP1, 1>(acc1, sb, lid);
    sts_chunk(smem, 2, tid, p0);
    ldg_chunk(xg, 3, tid, p1);
    __syncthreads();

    // c = 2
    grp_chunk<RT0, NS0, CP0, 2>(acc0, sb, lid);
    if constexpr (NS1 > 0) grp_chunk<RT1, NS1, CP1, 2>(acc1, sb, lid);
    sts_chunk(smem, 3, tid, p1);
    __syncthreads();

    // c = 3
    grp_chunk<RT0, NS0, CP0, 3>(acc0, sb, lid);
    if constexpr (NS1 > 0) grp_chunk<RT1, NS1, CP1, 3>(acc1, sb, lid);

    // epilogue
    store_grp<RT0, NS0, CP0>(acc0, ob, lid);
    if constexpr (NS1 > 0) store_grp<RT1, NS1, CP1>(acc1, ob, lid);
}

__global__ void __launch_bounds__(128, 6) dotint_mma_kernel(const float* __restrict__ x,
                                                            float* __restrict__ out) {
    extern __shared__ char smem[];
    const uint32_t sb = smem_u32(smem);
    const int tid = threadIdx.x;
    const int lid = tid & 31;
    const int wid = tid >> 5;

    const float4* xg = reinterpret_cast<const float4*>(x) + (size_t)blockIdx.x * 2048;
    float* ob = out + (size_t)blockIdx.x * NPAIR;

    switch (wid) {
        case 0: warp_main<0, 1, 0, 3, 1, 3>(sb, smem, xg, ob, tid, lid); break;  // (0,0-1)+(3,6-7)
        case 1: warp_main<0, 2, 1, 0, 0, 0>(sb, smem, xg, ob, tid, lid); break;  // rt0-1 x cols 2,3
        case 2: warp_main<0, 3, 2, 0, 0, 0>(sb, smem, xg, ob, tid, lid); break;  // rt0-2 x cols 4,5
        default: warp_main<0, 3, 3, 0, 0, 0>(sb, smem, xg, ob, tid, lid); break; // rt0-2 x cols 6,7
    }
}

extern "C" void kernel_launch(void* const* d_in, const int* in_sizes, int n_in,
                              void* d_out, int out_size) {
    const float* x = (const float*)d_in[0];
    float* out = (float*)d_out;
    int nbatch = in_sizes[0] / (FF * 128);   // 16384
    cudaFuncSetAttribute(dotint_mma_kernel, cudaFuncAttributeMaxDynamicSharedMemorySize, SM_TOTAL);
    dotint_mma_kernel<<<nbatch, 128, SM_TOTAL>>>(x, out);
}

// round 10
// speedup vs baseline: 1.3293x; 1.3293x over previous
#include <cuda_runtime.h>
#include <cuda_bf16.h>
#include <cstdint>

// DotInteraction: x [16384, 64, 128] fp32 -> upper-tri gram [16384, 2016] fp32.
// mma.sync m16n8k16 bf16 + ldmatrix (tcgen05 unavailable: harness targets sm_103 w/o 'a').
// Precision: x = hi + lo (bf16); D = hh + hl + lh, fp32 accumulate (rel err ~4e-6).
// R10: gram-symmetry fragment reuse. For m16n8k16 with k-major storage, stripe s's
// A-frag regs {a0,a2} ARE the B-frag of cols 16s..+7, and {a1,a3} of cols 16s+8..+15.
// So each warp loads ONLY A-frags for its stripe set; B operands are register aliases.
// ldsm bytes -33% vs R7. Block partition (16x16 blocks of the 64x64 gram, upper 10):
//   w0: (0,0)(0,1)(1,1) stripes{0,1}   w1: (2,2)(2,3)(3,3) stripes{2,3}
//   w2: (0,2)(0,3)      stripes{0,2,3} w3: (1,2)(1,3)      stripes{1,2,3}
// Swizzle: byte(r, kc16) = (kc>>3)<<13 | r<<7 | (((kc&7)^(r&7))<<4)  [SW128 blocked atoms]

#define FF 64
#define NPAIR 2016

constexpr int MATB = 64 * 128 * 2;   // 16384 B per bf16 matrix, swizzled
constexpr int SM_TOTAL = 2 * MATB;   // [H][L] = 32768 B

__device__ __forceinline__ uint32_t smem_u32(const void* p) {
    uint32_t a;
    asm("{ .reg .u64 t; cvta.to.shared.u64 t, %1; cvt.u32.u64 %0, t; }" : "=r"(a) : "l"(p));
    return a;
}
__device__ __forceinline__ void ldsm_x4(uint32_t* r, uint32_t addr) {
    asm volatile("ldmatrix.sync.aligned.m8n8.x4.shared.b16 {%0,%1,%2,%3}, [%4];"
                 : "=r"(r[0]), "=r"(r[1]), "=r"(r[2]), "=r"(r[3]) : "r"(addr));
}
__device__ __forceinline__ void mma2(float* c, const uint32_t* a, uint32_t b0, uint32_t b1) {
    asm volatile(
        "mma.sync.aligned.m16n8k16.row.col.f32.bf16.bf16.f32 "
        "{%0,%1,%2,%3}, {%4,%5,%6,%7}, {%8,%9}, {%0,%1,%2,%3};"
        : "+f"(c[0]), "+f"(c[1]), "+f"(c[2]), "+f"(c[3])
        : "r"(a[0]), "r"(a[1]), "r"(a[2]), "r"(a[3]), "r"(b0), "r"(b1));
}
__device__ __forceinline__ uint32_t cvt_bf16x2(float hi, float lo) {
    uint32_t r;
    asm("cvt.rn.bf16x2.f32 %0, %1, %2;" : "=r"(r) : "f"(hi), "f"(lo));
    return r;
}

// Warp body: NS stripes (values S0..S2), NB blocks given as (index-into-stripe-list) pairs.
template <int NS, int NB, int S0, int S1, int S2,
          int B0s, int B0c, int B1s, int B1c, int B2s, int B2c>
__device__ __forceinline__ void run_warp(uint32_t sb, float* __restrict__ ob, int lid) {
    const int stripes[3] = {S0, S1, S2};
    const int bs[3] = {B0s, B1s, B2s};
    const int bc[3] = {B0c, B1c, B2c};

    float acc[NB][8];
#pragma unroll
    for (int b = 0; b < NB; ++b)
#pragma unroll
        for (int e = 0; e < 8; ++e) acc[b][e] = 0.0f;

    // ldmatrix lane address mapping (A m16k16 x4): lanes 0-15 rows (lid&15) k-lo chunk,
    // lanes 16-31 same rows k-hi chunk. Produces regs {a0,a1,a2,a3}.
    const int hA = lid >> 4;
    const uint32_t mA4 = (uint32_t)(((lid & 7) ^ hA) << 4);
    const uint32_t base = sb + ((uint32_t)(lid & 15) << 7);

#pragma unroll
    for (int kk = 0; kk < 8; ++kk) {
        const uint32_t koff = (uint32_t)((kk >> 2) << 13);
        const uint32_t cx = ((uint32_t)(((2 * kk) & 7) << 4)) ^ mA4;

        uint32_t fh[NS][4], fl[NS][4];
#pragma unroll
        for (int s = 0; s < NS; ++s) {
            const uint32_t ad = base + (uint32_t)(stripes[s] * 2048) + koff + cx;
            ldsm_x4(fh[s], ad);
            ldsm_x4(fl[s], ad + MATB);
        }

#pragma unroll
        for (int b = 0; b < NB; ++b) {
            const int si = bs[b], ci = bc[b];
            // tile0: cols 16C..+7  -> B regs {r0, r2} of stripe C's frag
            mma2(acc[b] + 0, fh[si], fh[ci][0], fh[ci][2]);   // hh
            mma2(acc[b] + 0, fh[si], fl[ci][0], fl[ci][2]);   // hl
            mma2(acc[b] + 0, fl[si], fh[ci][0], fh[ci][2]);   // lh
            // tile1: cols 16C+8..+15 -> B regs {r1, r3}
            mma2(acc[b] + 4, fh[si], fh[ci][1], fh[ci][3]);
            mma2(acc[b] + 4, fh[si], fl[ci][1], fl[ci][3]);
            mma2(acc[b] + 4, fl[si], fh[ci][1], fh[ci][3]);
        }
    }

    // epilogue: D frag -> thread (row S*16 + lid/4 (+8), col 16C + 8cc + 2(lid%4) + d)
    const int rb0 = lid >> 2;
    const int cb0 = 2 * (lid & 3);
#pragma unroll
    for (int b = 0; b < NB; ++b) {
        const int S = stripes[bs[b]], C = stripes[bc[b]];
        const bool diag = (S == C);          // compile-time after unroll
        const int ib = S * 16 + rb0;
#pragma unroll
        for (int cc = 0; cc < 2; ++cc) {
            const int j0 = 16 * C + 8 * cc + cb0;
#pragma unroll
            for (int half = 0; half < 2; ++half) {
                const int i = ib + 8 * half;
                const int rowoff = i * (2 * FF - i - 1) / 2 - i - 1;  // out idx = rowoff + j
#pragma unroll
                for (int d = 0; d < 2; ++d) {
                    const int j = j0 + d;
                    if (!diag || j > i) ob[rowoff + j] = acc[b][4 * cc + 2 * half + d];
                }
            }
        }
    }
}

__global__ void __launch_bounds__(128, 7) dotint_mma_kernel(const float* __restrict__ x,
                                                            float* __restrict__ out) {
    extern __shared__ char smem[];
    const uint32_t sb = smem_u32(smem);
    const int tid = threadIdx.x;
    const int lid = tid & 31;
    const int wid = tid >> 5;

    // ---- load batch (2048 float4), split hi/lo bf16 (packed cvt), store swizzled ----
    const float4* xg = reinterpret_cast<const float4*>(x) + (size_t)blockIdx.x * 2048;
#pragma unroll
    for (int it = 0; it < 16; ++it) {
        int idx = tid + it * 128;          // 0..2047
        int r = idx >> 5;                  // row 0..63
        int kc = (idx & 31) >> 1;          // 16B chunk 0..15
        int sub = (idx & 1) << 3;          // byte offset within chunk
        float4 v = xg[idx];

        uint32_t hp0 = cvt_bf16x2(v.y, v.x);
        uint32_t hp1 = cvt_bf16x2(v.w, v.z);
        float h0 = __uint_as_float(hp0 << 16);
        float h1 = __uint_as_float(hp0 & 0xffff0000u);
        float h2 = __uint_as_float(hp1 << 16);
        float h3 = __uint_as_float(hp1 & 0xffff0000u);
        uint32_t lp0 = cvt_bf16x2(v.y - h1, v.x - h0);
        uint32_t lp1 = cvt_bf16x2(v.w - h3, v.z - h2);

        uint32_t off = ((uint32_t)(kc >> 3) << 13) + ((uint32_t)r << 7) +
                       ((uint32_t)(((kc & 7) ^ (r & 7)) << 4)) + (uint32_t)sub;
        *reinterpret_cast<uint2*>(smem + off) = make_uint2(hp0, hp1);
        *reinterpret_cast<uint2*>(smem + MATB + off) = make_uint2(lp0, lp1);
    }
    __syncthreads();

    // ---- compute: symmetry-partitioned 16x16 blocks ----
    float* ob = out + (size_t)blockIdx.x * NPAIR;
    switch (wid) {
        case 0:  // blocks (0,0) (0,1) (1,1); stripes {0,1}
            run_warp<2, 3, 0, 1, 0, 0, 0, 0, 1, 1, 1>(sb, ob, lid);
            break;
        case 1:  // blocks (2,2) (2,3) (3,3); stripes {2,3}
            run_warp<2, 3, 2, 3, 0, 0, 0, 0, 1, 1, 1>(sb, ob, lid);
            break;
        case 2:  // blocks (0,2) (0,3); stripes {0,2,3}
            run_warp<3, 2, 0, 2, 3, 0, 1, 0, 2, 0, 0>(sb, ob, lid);
            break;
        default: // blocks (1,2) (1,3); stripes {1,2,3}
            run_warp<3, 2, 1, 2, 3, 0, 1, 0, 2, 0, 0>(sb, ob, lid);
            break;
    }
}

extern "C" void kernel_launch(void* const* d_in, const int* in_sizes, int n_in,
                              void* d_out, int out_size) {
    const float* x = (const float*)d_in[0];
    float* out = (float*)d_out;
    int nbatch = in_sizes[0] / (FF * 128);   // 16384
    cudaFuncSetAttribute(dotint_mma_kernel, cudaFuncAttributeMaxDynamicSharedMemorySize, SM_TOTAL);
    dotint_mma_kernel<<<nbatch, 128, SM_TOTAL>>>(x, out);
}

// round 11
// speedup vs baseline: 1.8648x; 1.4028x over previous
#include <cuda_runtime.h>
#include <cuda_fp16.h>
#include <cstdint>

// DotInteraction: x [16384, 64, 128] fp32 -> upper-tri gram [16384, 2016] fp32.
// mma.sync m16n8k16 fp16 + ldmatrix (tcgen05 unavailable: harness targets sm_103 w/o 'a').
// R11: single-term fp16 gram. Per-product residual <= 2*2^-12 -> predicted global
// rel_err ~2-5e-4 (< 1e-3 threshold). Compute phase shrinks 3x (160 MMAs/batch),
// smem halves to 16KB -> 8 CTAs/SM. Gram-symmetry fragment aliasing from R10:
// stripe s's A-frag regs {r0,r2}/{r1,r3} ARE the B-frags of cols 16s..+7 / +8..+15.
// Block partition (16x16 blocks, upper 10):
//   w0: (0,0)(0,1)(1,1) stripes{0,1}   w1: (2,2)(2,3)(3,3) stripes{2,3}
//   w2: (0,2)(0,3)      stripes{0,2,3} w3: (1,2)(1,3)      stripes{1,2,3}
// Swizzle: byte(r, kc16) = (kc>>3)<<13 | r<<7 | (((kc&7)^(r&7))<<4)  [SW128 blocked atoms]

#define FF 64
#define NPAIR 2016

constexpr int MATB = 64 * 128 * 2;   // 16384 B: single fp16 matrix, swizzled
constexpr int SM_TOTAL = MATB;

__device__ __forceinline__ uint32_t smem_u32(const void* p) {
    uint32_t a;
    asm("{ .reg .u64 t; cvta.to.shared.u64 t, %1; cvt.u32.u64 %0, t; }" : "=r"(a) : "l"(p));
    return a;
}
__device__ __forceinline__ void ldsm_x4(uint32_t* r, uint32_t addr) {
    asm volatile("ldmatrix.sync.aligned.m8n8.x4.shared.b16 {%0,%1,%2,%3}, [%4];"
                 : "=r"(r[0]), "=r"(r[1]), "=r"(r[2]), "=r"(r[3]) : "r"(addr));
}
__device__ __forceinline__ void mma2(float* c, const uint32_t* a, uint32_t b0, uint32_t b1) {
    asm volatile(
        "mma.sync.aligned.m16n8k16.row.col.f32.f16.f16.f32 "
        "{%0,%1,%2,%3}, {%4,%5,%6,%7}, {%8,%9}, {%0,%1,%2,%3};"
        : "+f"(c[0]), "+f"(c[1]), "+f"(c[2]), "+f"(c[3])
        : "r"(a[0]), "r"(a[1]), "r"(a[2]), "r"(a[3]), "r"(b0), "r"(b1));
}
__device__ __forceinline__ uint32_t cvt_f16x2(float hi, float lo) {
    uint32_t r;
    asm("cvt.rn.f16x2.f32 %0, %1, %2;" : "=r"(r) : "f"(hi), "f"(lo));
    return r;
}

// Warp body: NS stripes (values S0..S2), NB blocks as (index-into-stripe-list) pairs.
template <int NS, int NB, int S0, int S1, int S2,
          int B0s, int B0c, int B1s, int B1c, int B2s, int B2c>
__device__ __forceinline__ void run_warp(uint32_t sb, float* __restrict__ ob, int lid) {
    const int stripes[3] = {S0, S1, S2};
    const int bs[3] = {B0s, B1s, B2s};
    const int bc[3] = {B0c, B1c, B2c};

    float acc[NB][8];
#pragma unroll
    for (int b = 0; b < NB; ++b)
#pragma unroll
        for (int e = 0; e < 8; ++e) acc[b][e] = 0.0f;

    const int hA = lid >> 4;
    const uint32_t mA4 = (uint32_t)(((lid & 7) ^ hA) << 4);
    const uint32_t base = sb + ((uint32_t)(lid & 15) << 7);

#pragma unroll
    for (int kk = 0; kk < 8; ++kk) {
        const uint32_t koff = (uint32_t)((kk >> 2) << 13);
        const uint32_t cx = ((uint32_t)(((2 * kk) & 7) << 4)) ^ mA4;

        uint32_t fh[NS][4];
#pragma unroll
        for (int s = 0; s < NS; ++s)
            ldsm_x4(fh[s], base + (uint32_t)(stripes[s] * 2048) + koff + cx);

#pragma unroll
        for (int b = 0; b < NB; ++b) {
            const int si = bs[b], ci = bc[b];
            mma2(acc[b] + 0, fh[si], fh[ci][0], fh[ci][2]);   // cols 16C..+7
            mma2(acc[b] + 4, fh[si], fh[ci][1], fh[ci][3]);   // cols 16C+8..+15
        }
    }

    // epilogue: thread t -> (row S*16 + t/4 (+8), col 16C + 8cc + 2(t%4) + d)
    const int rb0 = lid >> 2;
    const int cb0 = 2 * (lid & 3);
#pragma unroll
    for (int b = 0; b < NB; ++b) {
        const int S = stripes[bs[b]], C = stripes[bc[b]];
        const bool diag = (S == C);
        const int ib = S * 16 + rb0;
#pragma unroll
        for (int cc = 0; cc < 2; ++cc) {
            const int j0 = 16 * C + 8 * cc + cb0;
#pragma unroll
            for (int half = 0; half < 2; ++half) {
                const int i = ib + 8 * half;
                const int rowoff = i * (2 * FF - i - 1) / 2 - i - 1;  // out idx = rowoff + j
#pragma unroll
                for (int d = 0; d < 2; ++d) {
                    const int j = j0 + d;
                    if (!diag || j > i) ob[rowoff + j] = acc[b][4 * cc + 2 * half + d];
                }
            }
        }
    }
}

__global__ void __launch_bounds__(128, 8) dotint_mma_kernel(const float* __restrict__ x,
                                                            float* __restrict__ out) {
    extern __shared__ char smem[];
    const uint32_t sb = smem_u32(smem);
    const int tid = threadIdx.x;
    const int lid = tid & 31;
    const int wid = tid >> 5;

    // ---- load batch (2048 float4), convert fp32->fp16 packed, store swizzled ----
    const float4* xg = reinterpret_cast<const float4*>(x) + (size_t)blockIdx.x * 2048;
#pragma unroll
    for (int it = 0; it < 16; ++it) {
        int idx = tid + it * 128;          // 0..2047
        int r = idx >> 5;                  // row 0..63
        int kc = (idx & 31) >> 1;          // 16B chunk 0..15
        int sub = (idx & 1) << 3;          // byte offset within chunk
        float4 v = xg[idx];

        uint32_t p0 = cvt_f16x2(v.y, v.x);
        uint32_t p1 = cvt_f16x2(v.w, v.z);

        uint32_t off = ((uint32_t)(kc >> 3) << 13) + ((uint32_t)r << 7) +
                       ((uint32_t)(((kc & 7) ^ (r & 7)) << 4)) + (uint32_t)sub;
        *reinterpret_cast<uint2*>(smem + off) = make_uint2(p0, p1);
    }
    __syncthreads();

    // ---- compute: symmetry-partitioned 16x16 blocks ----
    float* ob = out + (size_t)blockIdx.x * NPAIR;
    switch (wid) {
        case 0:  // blocks (0,0) (0,1) (1,1); stripes {0,1}
            run_warp<2, 3, 0, 1, 0, 0, 0, 0, 1, 1, 1>(sb, ob, lid);
            break;
        case 1:  // blocks (2,2) (2,3) (3,3); stripes {2,3}
            run_warp<2, 3, 2, 3, 0, 0, 0, 0, 1, 1, 1>(sb, ob, lid);
            break;
        case 2:  // blocks (0,2) (0,3); stripes {0,2,3}
            run_warp<3, 2, 0, 2, 3, 0, 1, 0, 2, 0, 0>(sb, ob, lid);
            break;
        default: // blocks (1,2) (1,3); stripes {1,2,3}
            run_warp<3, 2, 1, 2, 3, 0, 1, 0, 2, 0, 0>(sb, ob, lid);
            break;
    }
}

extern "C" void kernel_launch(void* const* d_in, const int* in_sizes, int n_in,
                              void* d_out, int out_size) {
    const float* x = (const float*)d_in[0];
    float* out = (float*)d_out;
    int nbatch = in_sizes[0] / (FF * 128);   // 16384
    cudaFuncSetAttribute(dotint_mma_kernel, cudaFuncAttributeMaxDynamicSharedMemorySize, SM_TOTAL);
    dotint_mma_kernel<<<nbatch, 128, SM_TOTAL>>>(x, out);
}